// round 4
// baseline (speedup 1.0000x reference)
#include <cuda_runtime.h>
#include <cuda_bf16.h>

namespace {
constexpr int B  = 2;
constexpr int S  = 2048;
constexpr int H  = 16;
constexpr int D  = 64;
constexpr int TQ = 64;   // query tile
constexpr int TK = 64;   // key tile
constexpr int NT = 256;  // threads per CTA
}

// Flash-attention style fp32 kernel.
// Grid: (B*H, S/TQ). Block: 256 threads as 16x16 (tx = col group, ty = row group),
// each thread owns a 4x4 micro-tile of the 64x64 score tile and a 4(row)x4(dcol)
// micro-tile of the output accumulator.
//
// smem:
//   qs[d][row]  - Q tile transposed, pre-scaled by sqrt(D)=8   (16 KB)
//   ks[d][col]  - K tile transposed; reused as ps[row][kk]     (16 KB)
//   vs[kk][d]   - V tile natural                               (16 KB)
__global__ void __launch_bounds__(NT, 3)
attn_fp32_kernel(const float* __restrict__ gq, const float* __restrict__ gk,
                 const float* __restrict__ gv, const float* __restrict__ gbias,
                 const int*   __restrict__ gmask, float* __restrict__ gout)
{
    __shared__ float qs[D][TQ];
    __shared__ float ks[D][TK];
    __shared__ float vs[TK][D];
    float (*ps)[TK] = ks;   // alias: P tile (natural [row][kk]) reuses K buffer

    const int tid = threadIdx.x;
    const int tx  = tid & 15;        // col group (4 cols)
    const int ty  = tid >> 4;        // row group (4 rows)
    const int bh  = blockIdx.x;      // b*H + h  (matches bias [B,H,S,S] layout)
    const int b   = bh >> 4;
    const int h   = bh & 15;
    const int q0  = blockIdx.y * TQ;

    // Lane mapping for the transposed Q/K staging:
    //   cc = row-in-tile varies across lanes -> STS bank = cc mod 32 -> <=2-way conflict.
    //   Adjacent lane pairs (l, l+16) cover 32B contiguous gmem -> full sector use.
    const int cc = (tid & 15) | ((tid >> 6) << 4);   // 0..63
    const int d0 = ((tid >> 4) & 3) << 2;            // 0,4,8,12

    // ---- load Q tile (transposed, pre-scaled by 8; exact in fp32) ----
    {
        const float* qb = gq + ((size_t)(b * S + q0) * H + h) * D;
        #pragma unroll
        for (int rep = 0; rep < 4; rep++) {
            const int dv = d0 + (rep << 4);
            float4 t = *reinterpret_cast<const float4*>(qb + (size_t)cc * (H * D) + dv);
            qs[dv + 0][cc] = t.x * 8.0f;
            qs[dv + 1][cc] = t.y * 8.0f;
            qs[dv + 2][cc] = t.z * 8.0f;
            qs[dv + 3][cc] = t.w * 8.0f;
        }
    }

    float acc[4][4] = {};
    float mrow[4] = {-1e30f, -1e30f, -1e30f, -1e30f};
    float lrow[4] = {0.f, 0.f, 0.f, 0.f};

    const float* kb0 = gk + ((size_t)(b * S) * H + h) * D;
    const float* vb0 = gv + ((size_t)(b * S) * H + h) * D;

    for (int k0 = 0; k0 < S; k0 += TK) {
        __syncthreads();   // previous iteration's PV finished reading ps/vs

        // ---- stage K (transposed) and V (natural) ----
        {
            const float* kb = kb0 + (size_t)k0 * (H * D);
            #pragma unroll
            for (int rep = 0; rep < 4; rep++) {
                const int dv = d0 + (rep << 4);
                float4 t = *reinterpret_cast<const float4*>(kb + (size_t)cc * (H * D) + dv);
                ks[dv + 0][cc] = t.x;
                ks[dv + 1][cc] = t.y;
                ks[dv + 2][cc] = t.z;
                ks[dv + 3][cc] = t.w;
            }
            const float* vb = vb0 + (size_t)k0 * (H * D);
            #pragma unroll
            for (int rep = 0; rep < 4; rep++) {
                const int idx = tid + rep * NT;
                const int kk  = idx >> 4;
                const int dv  = (idx & 15) << 2;
                *reinterpret_cast<float4*>(&vs[kk][dv]) =
                    *reinterpret_cast<const float4*>(vb + (size_t)kk * (H * D) + dv);
            }
        }
        __syncthreads();

        // ---- S = (Q*8) K^T : 16 FMA per d-step, 2 LDS.128 (both conflict-free) ----
        float sv[4][4] = {};
        #pragma unroll 8
        for (int d = 0; d < D; d++) {
            const float4 qv = *reinterpret_cast<const float4*>(&qs[d][ty << 2]);
            const float4 kv = *reinterpret_cast<const float4*>(&ks[d][tx << 2]);
            const float qa[4] = {qv.x, qv.y, qv.z, qv.w};
            const float ka[4] = {kv.x, kv.y, kv.z, kv.w};
            #pragma unroll
            for (int i = 0; i < 4; i++)
                #pragma unroll
                for (int j = 0; j < 4; j++)
                    sv[i][j] = fmaf(qa[i], ka[j], sv[i][j]);
        }

        // ---- bias add, mask->0, online softmax update ----
        #pragma unroll
        for (int i = 0; i < 4; i++) {
            const int row = q0 + (ty << 2) + i;
            const float4 bv = *reinterpret_cast<const float4*>(
                gbias + ((size_t)bh * S + row) * S + k0 + (tx << 2));
            const int4 mv = *reinterpret_cast<const int4*>(
                gmask + ((size_t)b * S + row) * S + k0 + (tx << 2));
            sv[i][0] = mv.x ? 0.0f : sv[i][0] + bv.x;
            sv[i][1] = mv.y ? 0.0f : sv[i][1] + bv.y;
            sv[i][2] = mv.z ? 0.0f : sv[i][2] + bv.z;
            sv[i][3] = mv.w ? 0.0f : sv[i][3] + bv.w;

            float mx = fmaxf(fmaxf(sv[i][0], sv[i][1]), fmaxf(sv[i][2], sv[i][3]));
            #pragma unroll
            for (int off = 8; off; off >>= 1)
                mx = fmaxf(mx, __shfl_xor_sync(0xffffffffu, mx, off));
            const float mnew = fmaxf(mrow[i], mx);
            const float corr = __expf(mrow[i] - mnew);
            mrow[i] = mnew;

            float rs = 0.f;
            #pragma unroll
            for (int j = 0; j < 4; j++) {
                sv[i][j] = __expf(sv[i][j] - mnew);
                rs += sv[i][j];
            }
            #pragma unroll
            for (int off = 8; off; off >>= 1)
                rs += __shfl_xor_sync(0xffffffffu, rs, off);
            lrow[i] = lrow[i] * corr + rs;
            #pragma unroll
            for (int j = 0; j < 4; j++) acc[i][j] *= corr;
        }

        __syncthreads();   // all warps done reading ks before overwriting with P

        // ---- write P (natural [row][kk], vectorized, conflict-free) ----
        #pragma unroll
        for (int i = 0; i < 4; i++) {
            const float4 pw = make_float4(sv[i][0], sv[i][1], sv[i][2], sv[i][3]);
            *reinterpret_cast<float4*>(&ps[(ty << 2) + i][tx << 2]) = pw;
        }
        __syncthreads();

        // ---- O += P V : p reads are same-address broadcasts, v is vector ----
        #pragma unroll 4
        for (int kk = 0; kk < TK; kk++) {
            const float4 vv = *reinterpret_cast<const float4*>(&vs[kk][tx << 2]);
            const float va[4] = {vv.x, vv.y, vv.z, vv.w};
            #pragma unroll
            for (int i = 0; i < 4; i++) {
                const float p = ps[(ty << 2) + i][kk];
                #pragma unroll
                for (int j = 0; j < 4; j++)
                    acc[i][j] = fmaf(p, va[j], acc[i][j]);
            }
        }
    }

    // ---- epilogue: normalize and store [B,S,H,D] ----
    #pragma unroll
    for (int i = 0; i < 4; i++) {
        const float inv = 1.0f / lrow[i];
        const int row = q0 + (ty << 2) + i;
        const float4 o = make_float4(acc[i][0] * inv, acc[i][1] * inv,
                                     acc[i][2] * inv, acc[i][3] * inv);
        *reinterpret_cast<float4*>(
            gout + ((size_t)(b * S + row) * H + h) * D + (tx << 2)) = o;
    }
}

extern "C" void kernel_launch(void* const* d_in, const int* in_sizes, int n_in,
                              void* d_out, int out_size) {
    const float* q    = (const float*)d_in[0];
    const float* k    = (const float*)d_in[1];
    const float* v    = (const float*)d_in[2];
    const float* bias = (const float*)d_in[3];
    const int*   mask = (const int*)d_in[4];   // bool in reference -> int32 here; nonzero = masked
    float* out = (float*)d_out;

    dim3 grid(B * H, S / TQ);
    attn_fp32_kernel<<<grid, NT>>>(q, k, v, bias, mask, out);
}